// round 10
// baseline (speedup 1.0000x reference)
#include <cuda_runtime.h>
#include <cuda_bf16.h>
#include <math.h>

#define N_NODES 50000
#define DIM     64
#define NHEAD   8
#define NEDGE   800000
#define NEG_SLOPE 0.2f

#define SCAN_BLK  1024
#define SCAN_NBLK ((N_NODES + SCAN_BLK - 1) / SCAN_BLK)   // 49

// Scratch (device globals). INVARIANT: g_deg zero at module load and re-zeroed
// by fill_kernel each call.
__device__ float g_sdst[N_NODES * NHEAD];
__device__ float g_ssrc[N_NODES * NHEAD];
__device__ int   g_deg[N_NODES];
__device__ int   g_row[N_NODES + 1];
__device__ int   g_cursor[N_NODES];
__device__ int   g_csr_src[NEDGE];
__device__ float g_csr_ex[(size_t)NEDGE * NHEAD];

__device__ __forceinline__ float lrelu(float v) {
    return v >= 0.0f ? v : NEG_SLOPE * v;
}

// ---------------------------------------------------------------------------
// Kernel 1: per-node scores (warp computes 2 nodes) + fused degree histogram.
__global__ void scores_hist_kernel(const float* __restrict__ h_t,
                                   const float* __restrict__ att,
                                   const int* __restrict__ ei) {
    __shared__ float s_att[NHEAD * 2 * DIM];
    for (int i = threadIdx.x; i < NHEAD * 2 * DIM; i += blockDim.x)
        s_att[i] = att[i];
    __syncthreads();

    int idx = blockIdx.x * blockDim.x + threadIdx.x;
    if (idx >= NEDGE) return;

    atomicAdd(&g_deg[ei[NEDGE + idx]], 1);

    int lane = threadIdx.x & 31;
    int half = lane >> 4;
    int sub  = lane & 15;
    int n = (idx >> 5) * 2 + half;

    const float4 x = ((const float4*)(h_t + (size_t)n * DIM))[sub];

    float acc[16];
#pragma unroll
    for (int c = 0; c < 16; c++) {
        const float4 a = *(const float4*)(s_att + (c & 7) * 128 + (c >> 3) * 64 + sub * 4);
        acc[c] = x.x * a.x + x.y * a.y + x.z * a.z + x.w * a.w;
    }
#pragma unroll
    for (int o = 8; o > 0; o >>= 1) {
#pragma unroll
        for (int c = 0; c < 16; c++)
            acc[c] += __shfl_xor_sync(0xffffffffu, acc[c], o);
    }
    if (sub == 0) {
        float4* pd = (float4*)(g_sdst + n * NHEAD);
        float4* ps = (float4*)(g_ssrc + n * NHEAD);
        pd[0] = make_float4(acc[0], acc[1], acc[2], acc[3]);
        pd[1] = make_float4(acc[4], acc[5], acc[6], acc[7]);
        ps[0] = make_float4(acc[8], acc[9], acc[10], acc[11]);
        ps[1] = make_float4(acc[12], acc[13], acc[14], acc[15]);
    }
}

// ---------------------------------------------------------------------------
// Kernel 2: single-kernel scan; each block self-computes its prefix.
__global__ void scan_kernel() {
    __shared__ int sh[SCAN_BLK];
    __shared__ int red[32];
    __shared__ int s_boff;
    int t = threadIdx.x;
    int bid = blockIdx.x;

    int limit = bid * SCAN_BLK;
    int acc = 0;
    for (int i = t; i < limit; i += SCAN_BLK) acc += g_deg[i];
#pragma unroll
    for (int o = 16; o > 0; o >>= 1)
        acc += __shfl_down_sync(0xffffffffu, acc, o);
    if ((t & 31) == 0) red[t >> 5] = acc;
    __syncthreads();
    if (t < 32) {
        int w = red[t];
#pragma unroll
        for (int o = 16; o > 0; o >>= 1)
            w += __shfl_down_sync(0xffffffffu, w, o);
        if (t == 0) s_boff = w;
    }

    int i = bid * SCAN_BLK + t;
    int d = (i < N_NODES) ? g_deg[i] : 0;
    sh[t] = d;
    __syncthreads();
    for (int o = 1; o < SCAN_BLK; o <<= 1) {
        int u = (t >= o) ? sh[t - o] : 0;
        __syncthreads();
        sh[t] += u;
        __syncthreads();
    }
    if (i < N_NODES) {
        int excl = s_boff + sh[t] - d;
        g_row[i] = excl;
        g_cursor[i] = excl;
    }
    if (i == N_NODES - 1) g_row[N_NODES] = NEDGE;
}

// ---------------------------------------------------------------------------
// Kernel 3: fill CSR + per-edge exp for 8 heads; 4 edges per thread for MLP
// (int4 edge loads, 4 atomics + 8 random gathers in flight). Re-zeroes g_deg.
__global__ void fill_kernel(const int* __restrict__ ei) {
    int tid = blockIdx.x * blockDim.x + threadIdx.x;
    if (tid < N_NODES) g_deg[tid] = 0;
    if (tid >= NEDGE / 4) return;

    const int4 src4 = ((const int4*)ei)[tid];
    const int4 dst4 = ((const int4*)(ei + NEDGE))[tid];
    int srcs[4] = {src4.x, src4.y, src4.z, src4.w};
    int dsts[4] = {dst4.x, dst4.y, dst4.z, dst4.w};

    int ps[4];
#pragma unroll
    for (int k = 0; k < 4; k++)
        ps[k] = atomicAdd(&g_cursor[dsts[k]], 1);

    // issue all 16 gathers before consuming
    float4 d0[4], d1[4], s0[4], s1[4];
#pragma unroll
    for (int k = 0; k < 4; k++) {
        const float4* pd = (const float4*)(g_sdst + dsts[k] * NHEAD);
        const float4* pp = (const float4*)(g_ssrc + srcs[k] * NHEAD);
        d0[k] = pd[0]; d1[k] = pd[1];
        s0[k] = pp[0]; s1[k] = pp[1];
    }

#pragma unroll
    for (int k = 0; k < 4; k++) {
        float4 e0, e1;
        e0.x = __expf(lrelu(d0[k].x + s0[k].x));
        e0.y = __expf(lrelu(d0[k].y + s0[k].y));
        e0.z = __expf(lrelu(d0[k].z + s0[k].z));
        e0.w = __expf(lrelu(d0[k].w + s0[k].w));
        e1.x = __expf(lrelu(d1[k].x + s1[k].x));
        e1.y = __expf(lrelu(d1[k].y + s1[k].y));
        e1.z = __expf(lrelu(d1[k].z + s1[k].z));
        e1.w = __expf(lrelu(d1[k].w + s1[k].w));
        g_csr_src[ps[k]] = srcs[k];
        float4* pe = (float4*)(g_csr_ex + (size_t)ps[k] * NHEAD);
        pe[0] = e0;
        pe[1] = e1;
    }
}

// ---------------------------------------------------------------------------
// Kernel 4: aggregation + normalize + ELU. One warp per node.
// lane (h=lane>>2, q=lane&3) owns bytes {0,16,128,144} at row base + q*32
// (each LDG.128 hits ONE 128B line, immediate offsets). Scalar FFMA, no
// unroll — minimizes live regs so launch_bounds(128,10) lifts occupancy.
__global__ void __launch_bounds__(128, 10)
node_agg_kernel(const float* __restrict__ h_t, float* __restrict__ out) {
    int warp = (blockIdx.x * blockDim.x + threadIdx.x) >> 5;
    if (warp >= N_NODES) return;
    int lane = threadIdx.x & 31;
    int n = warp;
    int rs = g_row[n];
    int re = g_row[n + 1];

    int h = lane >> 2;
    int q = lane & 3;
    const char* hbase = (const char*)h_t + q * 32;   // + s*256 per edge

    float4 a0 = make_float4(0.f, 0.f, 0.f, 0.f);
    float4 a1 = a0, a2 = a0, a3 = a0;
    float denom = 0.0f;

    for (int base = rs; base < re; base += 32) {
        int cnt = re - base; if (cnt > 32) cnt = 32;
        int s = (lane < cnt) ? g_csr_src[base + lane] : 0;
        const char* exp0 = (const char*)(g_csr_ex + (size_t)base * NHEAD + h);

        for (int j = 0; j < cnt; j++) {
            int sj = __shfl_sync(0xffffffffu, s, j);
            float ex = *(const float*)(exp0 + (size_t)j * 32);
            const char* r = hbase + ((size_t)sj << 8);
            float4 x0 = *(const float4*)(r);
            float4 x1 = *(const float4*)(r + 16);
            float4 x2 = *(const float4*)(r + 128);
            float4 x3 = *(const float4*)(r + 144);
            denom += ex;
            a0.x += ex*x0.x; a0.y += ex*x0.y; a0.z += ex*x0.z; a0.w += ex*x0.w;
            a1.x += ex*x1.x; a1.y += ex*x1.y; a1.z += ex*x1.z; a1.w += ex*x1.w;
            a2.x += ex*x2.x; a2.y += ex*x2.y; a2.z += ex*x2.z; a2.w += ex*x2.w;
            a3.x += ex*x3.x; a3.y += ex*x3.y; a3.z += ex*x3.z; a3.w += ex*x3.w;
        }
    }

    float inv = (re > rs) ? 1.0f / denom : 0.0f;

    char* orow = (char*)out + ((size_t)n * (NHEAD * DIM) + h * DIM) * 4 + q * 32;
    float4 r4[4] = {a0, a1, a2, a3};
    const int offs[4] = {0, 16, 128, 144};
#pragma unroll
    for (int k = 0; k < 4; k++) {
        float4 x = r4[k];
        x.x *= inv; x.y *= inv; x.z *= inv; x.w *= inv;
        x.x = x.x > 0.f ? x.x : expm1f(x.x);
        x.y = x.y > 0.f ? x.y : expm1f(x.y);
        x.z = x.z > 0.f ? x.z : expm1f(x.z);
        x.w = x.w > 0.f ? x.w : expm1f(x.w);
        *(float4*)(orow + offs[k]) = x;
    }
}

// ---------------------------------------------------------------------------
extern "C" void kernel_launch(void* const* d_in, const int* in_sizes, int n_in,
                              void* d_out, int out_size) {
    const float* h_t = (const float*)d_in[0];
    const int*   ei  = (const int*)d_in[1];
    const float* att = (const float*)d_in[2];
    float*       out = (float*)d_out;

    scores_hist_kernel<<<(NEDGE + 255) / 256, 256>>>(h_t, att, ei);  // 1
    scan_kernel<<<SCAN_NBLK, SCAN_BLK>>>();                          // 2
    fill_kernel<<<(NEDGE / 4 + 255) / 256, 256>>>(ei);               // 3
    int blocks = (N_NODES * 32 + 127) / 128;
    node_agg_kernel<<<blocks, 128>>>(h_t, out);                      // 4 (ncu)
}

// round 11
// speedup vs baseline: 1.2001x; 1.2001x over previous
#include <cuda_runtime.h>
#include <cuda_bf16.h>
#include <math.h>

#define N_NODES 50000
#define DIM     64
#define NHEAD   8
#define NEDGE   800000
#define NEG_SLOPE 0.2f

#define SCAN_BLK  1024
#define SCAN_NBLK ((N_NODES + SCAN_BLK - 1) / SCAN_BLK)   // 49

// Scratch (device globals). INVARIANT: g_deg zero at module load and re-zeroed
// by fill_kernel each call.
__device__ float g_sdst[N_NODES * NHEAD];
__device__ float g_ssrc[N_NODES * NHEAD];
__device__ int   g_deg[N_NODES];
__device__ int   g_row[N_NODES + 1];
__device__ int   g_cursor[N_NODES];
__device__ int   g_csr_src[NEDGE];
__device__ float g_csr_ex[(size_t)NEDGE * NHEAD];

__device__ __forceinline__ float lrelu(float v) {
    return v >= 0.0f ? v : NEG_SLOPE * v;
}

// ---------------------------------------------------------------------------
// Kernel 1: per-node scores (warp computes 2 nodes) + fused degree histogram.
__global__ void scores_hist_kernel(const float* __restrict__ h_t,
                                   const float* __restrict__ att,
                                   const int* __restrict__ ei) {
    __shared__ float s_att[NHEAD * 2 * DIM];
    for (int i = threadIdx.x; i < NHEAD * 2 * DIM; i += blockDim.x)
        s_att[i] = att[i];
    __syncthreads();

    int idx = blockIdx.x * blockDim.x + threadIdx.x;
    if (idx >= NEDGE) return;

    atomicAdd(&g_deg[ei[NEDGE + idx]], 1);

    int lane = threadIdx.x & 31;
    int half = lane >> 4;
    int sub  = lane & 15;
    int n = (idx >> 5) * 2 + half;

    const float4 x = ((const float4*)(h_t + (size_t)n * DIM))[sub];

    float acc[16];
#pragma unroll
    for (int c = 0; c < 16; c++) {
        const float4 a = *(const float4*)(s_att + (c & 7) * 128 + (c >> 3) * 64 + sub * 4);
        acc[c] = x.x * a.x + x.y * a.y + x.z * a.z + x.w * a.w;
    }
#pragma unroll
    for (int o = 8; o > 0; o >>= 1) {
#pragma unroll
        for (int c = 0; c < 16; c++)
            acc[c] += __shfl_xor_sync(0xffffffffu, acc[c], o);
    }
    if (sub == 0) {
        float4* pd = (float4*)(g_sdst + n * NHEAD);
        float4* ps = (float4*)(g_ssrc + n * NHEAD);
        pd[0] = make_float4(acc[0], acc[1], acc[2], acc[3]);
        pd[1] = make_float4(acc[4], acc[5], acc[6], acc[7]);
        ps[0] = make_float4(acc[8], acc[9], acc[10], acc[11]);
        ps[1] = make_float4(acc[12], acc[13], acc[14], acc[15]);
    }
}

// ---------------------------------------------------------------------------
// Kernel 2: single-kernel scan; each block self-computes its prefix.
__global__ void scan_kernel() {
    __shared__ int sh[SCAN_BLK];
    __shared__ int red[32];
    __shared__ int s_boff;
    int t = threadIdx.x;
    int bid = blockIdx.x;

    int limit = bid * SCAN_BLK;
    int acc = 0;
    for (int i = t; i < limit; i += SCAN_BLK) acc += g_deg[i];
#pragma unroll
    for (int o = 16; o > 0; o >>= 1)
        acc += __shfl_down_sync(0xffffffffu, acc, o);
    if ((t & 31) == 0) red[t >> 5] = acc;
    __syncthreads();
    if (t < 32) {
        int w = red[t];
#pragma unroll
        for (int o = 16; o > 0; o >>= 1)
            w += __shfl_down_sync(0xffffffffu, w, o);
        if (t == 0) s_boff = w;
    }

    int i = bid * SCAN_BLK + t;
    int d = (i < N_NODES) ? g_deg[i] : 0;
    sh[t] = d;
    __syncthreads();
    for (int o = 1; o < SCAN_BLK; o <<= 1) {
        int u = (t >= o) ? sh[t - o] : 0;
        __syncthreads();
        sh[t] += u;
        __syncthreads();
    }
    if (i < N_NODES) {
        int excl = s_boff + sh[t] - d;
        g_row[i] = excl;
        g_cursor[i] = excl;
    }
    if (i == N_NODES - 1) g_row[N_NODES] = NEDGE;
}

// ---------------------------------------------------------------------------
// Kernel 3: fill CSR + per-edge exp for 8 heads; 4 edges per thread for MLP.
__global__ void fill_kernel(const int* __restrict__ ei) {
    int tid = blockIdx.x * blockDim.x + threadIdx.x;
    if (tid < N_NODES) g_deg[tid] = 0;
    if (tid >= NEDGE / 4) return;

    const int4 src4 = ((const int4*)ei)[tid];
    const int4 dst4 = ((const int4*)(ei + NEDGE))[tid];
    int srcs[4] = {src4.x, src4.y, src4.z, src4.w};
    int dsts[4] = {dst4.x, dst4.y, dst4.z, dst4.w};

    int ps[4];
#pragma unroll
    for (int k = 0; k < 4; k++)
        ps[k] = atomicAdd(&g_cursor[dsts[k]], 1);

    float4 d0[4], d1[4], s0[4], s1[4];
#pragma unroll
    for (int k = 0; k < 4; k++) {
        const float4* pd = (const float4*)(g_sdst + dsts[k] * NHEAD);
        const float4* pp = (const float4*)(g_ssrc + srcs[k] * NHEAD);
        d0[k] = pd[0]; d1[k] = pd[1];
        s0[k] = pp[0]; s1[k] = pp[1];
    }

#pragma unroll
    for (int k = 0; k < 4; k++) {
        float4 e0, e1;
        e0.x = __expf(lrelu(d0[k].x + s0[k].x));
        e0.y = __expf(lrelu(d0[k].y + s0[k].y));
        e0.z = __expf(lrelu(d0[k].z + s0[k].z));
        e0.w = __expf(lrelu(d0[k].w + s0[k].w));
        e1.x = __expf(lrelu(d1[k].x + s1[k].x));
        e1.y = __expf(lrelu(d1[k].y + s1[k].y));
        e1.z = __expf(lrelu(d1[k].z + s1[k].z));
        e1.w = __expf(lrelu(d1[k].w + s1[k].w));
        g_csr_src[ps[k]] = srcs[k];
        float4* pe = (float4*)(g_csr_ex + (size_t)ps[k] * NHEAD);
        pe[0] = e0;
        pe[1] = e1;
    }
}

// ---------------------------------------------------------------------------
// Kernel 4: aggregation + normalize + ELU. One warp per node.
// R8 loop structure (2-way unroll, scalar float4 FMA, 64-reg budget) +
// immediate-offset char addressing + cheap ELU (__expf-1, not expm1f).
// lane (h=lane>>2, q=lane&3) reads bytes {0,16,128,144} at rowbase + q*32:
// each LDG.128 hits ONE 128B line -> 4 wavefronts/edge.
__global__ void __launch_bounds__(128, 8)
node_agg_kernel(const float* __restrict__ h_t, float* __restrict__ out) {
    int warp = (blockIdx.x * blockDim.x + threadIdx.x) >> 5;
    if (warp >= N_NODES) return;
    int lane = threadIdx.x & 31;
    int n = warp;
    int rs = g_row[n];
    int re = g_row[n + 1];

    int h = lane >> 2;
    int q = lane & 3;
    const char* hbase = (const char*)h_t + q * 32;   // + s*256 per edge

    float4 a0 = make_float4(0.f, 0.f, 0.f, 0.f);
    float4 a1 = a0, a2 = a0, a3 = a0;
    float denom = 0.0f;

    for (int base = rs; base < re; base += 32) {
        int cnt = re - base; if (cnt > 32) cnt = 32;
        int s = (lane < cnt) ? g_csr_src[base + lane] : 0;
        const char* exp0 = (const char*)(g_csr_ex + (size_t)base * NHEAD + h);

        int j = 0;
        for (; j + 2 <= cnt; j += 2) {
            int s0 = __shfl_sync(0xffffffffu, s, j);
            int s1 = __shfl_sync(0xffffffffu, s, j + 1);
            float e0 = *(const float*)(exp0 + (size_t)j * 32);
            float e1 = *(const float*)(exp0 + (size_t)j * 32 + 32);

            const char* r0 = hbase + ((size_t)s0 << 8);
            const char* r1 = hbase + ((size_t)s1 << 8);
            float4 x00 = *(const float4*)(r0);
            float4 x01 = *(const float4*)(r0 + 16);
            float4 x02 = *(const float4*)(r0 + 128);
            float4 x03 = *(const float4*)(r0 + 144);
            float4 x10 = *(const float4*)(r1);
            float4 x11 = *(const float4*)(r1 + 16);
            float4 x12 = *(const float4*)(r1 + 128);
            float4 x13 = *(const float4*)(r1 + 144);

            denom += e0 + e1;

            a0.x += e0*x00.x; a0.y += e0*x00.y; a0.z += e0*x00.z; a0.w += e0*x00.w;
            a1.x += e0*x01.x; a1.y += e0*x01.y; a1.z += e0*x01.z; a1.w += e0*x01.w;
            a2.x += e0*x02.x; a2.y += e0*x02.y; a2.z += e0*x02.z; a2.w += e0*x02.w;
            a3.x += e0*x03.x; a3.y += e0*x03.y; a3.z += e0*x03.z; a3.w += e0*x03.w;

            a0.x += e1*x10.x; a0.y += e1*x10.y; a0.z += e1*x10.z; a0.w += e1*x10.w;
            a1.x += e1*x11.x; a1.y += e1*x11.y; a1.z += e1*x11.z; a1.w += e1*x11.w;
            a2.x += e1*x12.x; a2.y += e1*x12.y; a2.z += e1*x12.z; a2.w += e1*x12.w;
            a3.x += e1*x13.x; a3.y += e1*x13.y; a3.z += e1*x13.z; a3.w += e1*x13.w;
        }
        for (; j < cnt; j++) {
            int sj = __shfl_sync(0xffffffffu, s, j);
            float ex = *(const float*)(exp0 + (size_t)j * 32);
            const char* r = hbase + ((size_t)sj << 8);
            float4 x0 = *(const float4*)(r);
            float4 x1 = *(const float4*)(r + 16);
            float4 x2 = *(const float4*)(r + 128);
            float4 x3 = *(const float4*)(r + 144);
            denom += ex;
            a0.x += ex*x0.x; a0.y += ex*x0.y; a0.z += ex*x0.z; a0.w += ex*x0.w;
            a1.x += ex*x1.x; a1.y += ex*x1.y; a1.z += ex*x1.z; a1.w += ex*x1.w;
            a2.x += ex*x2.x; a2.y += ex*x2.y; a2.z += ex*x2.z; a2.w += ex*x2.w;
            a3.x += ex*x3.x; a3.y += ex*x3.y; a3.z += ex*x3.z; a3.w += ex*x3.w;
        }
    }

    float inv = (re > rs) ? 1.0f / denom : 0.0f;

    // ELU via fast path: v>0 ? v : __expf(v)-1  (expm1f is a slow software
    // routine; __expf is MUFU. abs err ~1e-7, zero-degree stays exactly 0)
    char* orow = (char*)out + ((size_t)n * (NHEAD * DIM) + h * DIM) * 4 + q * 32;
    float4 r4[4] = {a0, a1, a2, a3};
    const int offs[4] = {0, 16, 128, 144};
#pragma unroll
    for (int k = 0; k < 4; k++) {
        float4 x = r4[k];
        x.x *= inv; x.y *= inv; x.z *= inv; x.w *= inv;
        x.x = x.x > 0.f ? x.x : (__expf(x.x) - 1.0f);
        x.y = x.y > 0.f ? x.y : (__expf(x.y) - 1.0f);
        x.z = x.z > 0.f ? x.z : (__expf(x.z) - 1.0f);
        x.w = x.w > 0.f ? x.w : (__expf(x.w) - 1.0f);
        *(float4*)(orow + offs[k]) = x;
    }
}

// ---------------------------------------------------------------------------
extern "C" void kernel_launch(void* const* d_in, const int* in_sizes, int n_in,
                              void* d_out, int out_size) {
    const float* h_t = (const float*)d_in[0];
    const int*   ei  = (const int*)d_in[1];
    const float* att = (const float*)d_in[2];
    float*       out = (float*)d_out;

    scores_hist_kernel<<<(NEDGE + 255) / 256, 256>>>(h_t, att, ei);  // 1
    scan_kernel<<<SCAN_NBLK, SCAN_BLK>>>();                          // 2
    fill_kernel<<<(NEDGE / 4 + 255) / 256, 256>>>(ei);               // 3
    int blocks = (N_NODES * 32 + 127) / 128;
    node_agg_kernel<<<blocks, 128>>>(h_t, out);                      // 4 (ncu)
}